// round 12
// baseline (speedup 1.0000x reference)
#include <cuda_runtime.h>
#include <cuda_bf16.h>
#include <math.h>

// Problem constants
#define NROW 384          // N = 2*bs
#define BSZ  192
#define DIM  1024
#define NM1  383          // N-1
#define MDEN 56328576.0   // N*(N-1)^2
#define TK   48           // gram tile
#define NT   8            // tiles per side (384/48)
#define SROW 70           // smem row stride (floats): conflict-free f32x2 reads

// Scratch (device globals; no allocation allowed)
__device__ float g_d[4][NROW * NROW];   // per-kz partial dot planes
__device__ float g_sqp[4 * NROW];       // per-kz partial squared norms
__device__ float g_row[NROW];
__device__ int   g_cnt;                 // zero-init; last block resets -> replay-safe

__device__ __forceinline__ const float* frow(const float* f, int r) {
    return f + (r < BSZ ? r * (2 * DIM) : (r - BSZ) * (2 * DIM) + DIM);
}

// ---- packed f32x2 helpers ----
__device__ __forceinline__ unsigned long long pk2(float lo, float hi) {
    unsigned long long r;
    asm("mov.b64 %0, {%1, %2};" : "=l"(r) : "f"(lo), "f"(hi));
    return r;
}
__device__ __forceinline__ unsigned long long add2(unsigned long long a, unsigned long long b) {
    unsigned long long r;
    asm("add.rn.f32x2 %0, %1, %2;" : "=l"(r) : "l"(a), "l"(b));
    return r;
}
__device__ __forceinline__ unsigned long long fma2p(unsigned long long a, unsigned long long b,
                                                    unsigned long long c) {
    unsigned long long r;
    asm("fma.rn.f32x2 %0, %1, %2, %3;" : "=l"(r) : "l"(a), "l"(b), "l"(c));
    return r;
}
__device__ __forceinline__ unsigned long long abs2(unsigned long long a) {
    return a & 0x7FFFFFFF7FFFFFFFULL;
}
__device__ __forceinline__ float lanesum(unsigned long long a) {
    float lo, hi;
    asm("mov.b64 {%0, %1}, %2;" : "=f"(lo), "=f"(hi) : "l"(a));
    return lo + hi;
}

// ---------------------------------------------------------------------------
// Kernel 1: symmetric tiled Gram partials, packed-f32x2 inner loop,
// register-prefetch software pipeline (next chunk's LDGs overlap compute).
// Grid = 36 tile-pairs * 4 k-slices = 144 blocks (one wave).
// ---------------------------------------------------------------------------
__global__ __launch_bounds__(256) void gram_kernel(const float* __restrict__ feats) {
    __shared__ float As[TK][SROW];
    __shared__ float Bs[TK][SROW];

    int bid = blockIdx.x;
    int p = bid >> 2, kz = bid & 3;
    int a = 0, rem = p;
    while (rem >= NT - a) { rem -= NT - a; a++; }
    int b = a + rem;

    int tid = threadIdx.x;
    int ty = tid >> 4, tx = tid & 15;
    int r0 = a * TK, c0 = b * TK;
    int kbase = kz * 256;

    // load-slot geometry (3 slots cover 48 rows x 64 k-floats)
    int rr[3], kk4[3];
    const float* ap[3];
    const float* bp[3];
    #pragma unroll
    for (int it = 0; it < 3; it++) {
        int q = tid + it * 256;
        rr[it] = q >> 4;
        kk4[it] = (q & 15) << 2;
        ap[it] = frow(feats, r0 + rr[it]) + kk4[it];
        bp[it] = frow(feats, c0 + rr[it]) + kk4[it];
    }

    float4 av[3], bv[3], av2[3], bv2[3];
    #pragma unroll
    for (int it = 0; it < 3; it++) {
        av[it] = *(const float4*)(ap[it] + kbase);
        bv[it] = *(const float4*)(bp[it] + kbase);
    }

    unsigned long long acc[3][3] = {{0ull,0ull,0ull},{0ull,0ull,0ull},{0ull,0ull,0ull}};

    #pragma unroll
    for (int ch = 0; ch < 4; ch++) {
        // store current chunk
        #pragma unroll
        for (int it = 0; it < 3; it++) {
            *(float2*)&As[rr[it]][kk4[it]]     = make_float2(av[it].x, av[it].y);
            *(float2*)&As[rr[it]][kk4[it] + 2] = make_float2(av[it].z, av[it].w);
            *(float2*)&Bs[rr[it]][kk4[it]]     = make_float2(bv[it].x, bv[it].y);
            *(float2*)&Bs[rr[it]][kk4[it] + 2] = make_float2(bv[it].z, bv[it].w);
        }
        __syncthreads();
        // issue next chunk's loads (latency hidden under compute)
        if (ch < 3) {
            int kc = kbase + (ch + 1) * 64;
            #pragma unroll
            for (int it = 0; it < 3; it++) {
                av2[it] = *(const float4*)(ap[it] + kc);
                bv2[it] = *(const float4*)(bp[it] + kc);
            }
        }
        const unsigned long long* a0p = (const unsigned long long*)&As[3 * ty + 0][0];
        const unsigned long long* a1p = (const unsigned long long*)&As[3 * ty + 1][0];
        const unsigned long long* a2p = (const unsigned long long*)&As[3 * ty + 2][0];
        const unsigned long long* b0p = (const unsigned long long*)&Bs[3 * tx + 0][0];
        const unsigned long long* b1p = (const unsigned long long*)&Bs[3 * tx + 1][0];
        const unsigned long long* b2p = (const unsigned long long*)&Bs[3 * tx + 2][0];
        #pragma unroll
        for (int kk = 0; kk < 32; kk++) {
            unsigned long long a0 = a0p[kk], a1 = a1p[kk], a2 = a2p[kk];
            unsigned long long b0 = b0p[kk], b1 = b1p[kk], b2 = b2p[kk];
            acc[0][0] = fma2p(a0, b0, acc[0][0]);
            acc[0][1] = fma2p(a0, b1, acc[0][1]);
            acc[0][2] = fma2p(a0, b2, acc[0][2]);
            acc[1][0] = fma2p(a1, b0, acc[1][0]);
            acc[1][1] = fma2p(a1, b1, acc[1][1]);
            acc[1][2] = fma2p(a1, b2, acc[1][2]);
            acc[2][0] = fma2p(a2, b0, acc[2][0]);
            acc[2][1] = fma2p(a2, b1, acc[2][1]);
            acc[2][2] = fma2p(a2, b2, acc[2][2]);
        }
        __syncthreads();
        if (ch < 3) {
            #pragma unroll
            for (int it = 0; it < 3; it++) { av[it] = av2[it]; bv[it] = bv2[it]; }
        }
    }

    #pragma unroll
    for (int i2 = 0; i2 < 3; i2++) {
        #pragma unroll
        for (int j2 = 0; j2 < 3; j2++) {
            int r = r0 + 3 * ty + i2, c = c0 + 3 * tx + j2;
            float v = lanesum(acc[i2][j2]);
            g_d[kz][r * NROW + c] = v;
            g_d[kz][c * NROW + r] = v;
            if (r == c) g_sqp[kz * NROW + r] = v;
        }
    }
}

// ---------------------------------------------------------------------------
// block reduces for 192 threads (6 warps)
// ---------------------------------------------------------------------------
__device__ __forceinline__ float2 bred2(float2 v, float2* buf, int tid) {
    int lane = tid & 31, wid = tid >> 5;
    #pragma unroll
    for (int o = 16; o > 0; o >>= 1) {
        v.x += __shfl_xor_sync(0xffffffffu, v.x, o);
        v.y += __shfl_xor_sync(0xffffffffu, v.y, o);
    }
    if (lane == 0) buf[wid] = v;
    __syncthreads();
    if (tid < 8) {
        float2 w = (tid < 6) ? buf[tid] : make_float2(0.f, 0.f);
        #pragma unroll
        for (int o = 4; o > 0; o >>= 1) {
            w.x += __shfl_xor_sync(0xffu, w.x, o);
            w.y += __shfl_xor_sync(0xffu, w.y, o);
        }
        if (tid == 0) buf[0] = w;
    }
    __syncthreads();
    float2 r = buf[0];
    __syncthreads();
    return r;
}

__device__ __forceinline__ float4 bred4(float4 v, float4* buf, int tid) {
    int lane = tid & 31, wid = tid >> 5;
    #pragma unroll
    for (int o = 16; o > 0; o >>= 1) {
        v.x += __shfl_xor_sync(0xffffffffu, v.x, o);
        v.y += __shfl_xor_sync(0xffffffffu, v.y, o);
        v.z += __shfl_xor_sync(0xffffffffu, v.z, o);
        v.w += __shfl_xor_sync(0xffffffffu, v.w, o);
    }
    if (lane == 0) buf[wid] = v;
    __syncthreads();
    if (tid < 8) {
        float4 w = (tid < 6) ? buf[tid] : make_float4(0.f, 0.f, 0.f, 0.f);
        #pragma unroll
        for (int o = 4; o > 0; o >>= 1) {
            w.x += __shfl_xor_sync(0xffu, w.x, o);
            w.y += __shfl_xor_sync(0xffu, w.y, o);
            w.z += __shfl_xor_sync(0xffu, w.z, o);
            w.w += __shfl_xor_sync(0xffu, w.w, o);
        }
        if (tid == 0) buf[0] = w;
    }
    __syncthreads();
    float4 r = buf[0];
    __syncthreads();
    return r;
}

// ---------------------------------------------------------------------------
// Kernel 2 (R7/R11 structure): 192 threads/block, one row/block.
// Change vs R11: cntw transformed in place to per-(slot,bin) exclusive
// prefixes, so each scatter does ONE LDS instead of 6-18 predicated adds.
// rowsum = 2n*(S2z+S2b) - 4*C_half + P - Q
// ---------------------------------------------------------------------------
__global__ __launch_bounds__(192) void row_kernel(const int* __restrict__ labels,
                                                  float* __restrict__ out) {
    __shared__ float4 ext4[288];                // element pairs (2q, 2q+1 mod 383)
    __shared__ float  zs[NM1], bs[NM1];         // sorted scalars
    __shared__ short  gsA[NM1], geA[NM1];       // group bounds per sorted pos
    __shared__ int    cntw[12][52];             // counts -> exclusive slot prefixes
    __shared__ int    tot[52];
    __shared__ int    basev[52];
    __shared__ unsigned long long ymask;
    __shared__ float4 redbuf[6];
    __shared__ double dred[128];
    __shared__ int    isLast;

    int tid = threadIdx.x;
    int i = blockIdx.x;
    int lane = tid & 31, wid = tid >> 5;
    bool v1 = tid < 191;                        // second element valid

    {
        int* cw = &cntw[0][0];
        for (int idx = tid; idx < 12 * 52; idx += 192) cw[idx] = 0;
        if (tid == 0) ymask = 0ull;
    }
    __syncthreads();

    int labi = labels[i >= BSZ ? i - BSZ : i];
    float sq_i = g_sqp[i] + g_sqp[NROW + i] + g_sqp[2 * NROW + i] + g_sqp[3 * NROW + i];

    // ---- element 0: p0 = tid (always valid) ----
    float z0; int y0;
    {
        int jj = tid + (tid >= i);
        float dot = g_d[0][i * NROW + jj] + g_d[1][i * NROW + jj]
                  + g_d[2][i * NROW + jj] + g_d[3][i * NROW + jj];
        float sq_j = g_sqp[jj] + g_sqp[NROW + jj] + g_sqp[2 * NROW + jj] + g_sqp[3 * NROW + jj];
        z0 = sqrtf(fmaxf(sq_i + sq_j - 2.f * dot, 0.f));
        int labj = labels[jj >= BSZ ? jj - BSZ : jj];
        y0 = abs(labi - labj);
    }
    // ---- element 1: p1 = tid + 192 ----
    float z1 = 0.f; int y1 = 0;
    if (v1) {
        int p1 = tid + 192;
        int jj = p1 + (p1 >= i);
        float dot = g_d[0][i * NROW + jj] + g_d[1][i * NROW + jj]
                  + g_d[2][i * NROW + jj] + g_d[3][i * NROW + jj];
        float sq_j = g_sqp[jj] + g_sqp[NROW + jj] + g_sqp[2 * NROW + jj] + g_sqp[3 * NROW + jj];
        z1 = sqrtf(fmaxf(sq_i + sq_j - 2.f * dot, 0.f));
        int labj = labels[jj >= BSZ ? jj - BSZ : jj];
        y1 = abs(labi - labj);
    }

    atomicOr(&ymask, (1ull << y0) | (v1 ? (1ull << y1) : 0ull));

    unsigned mm0 = __match_any_sync(0xffffffffu, y0);
    if (lane == __ffs(mm0) - 1) atomicAdd(&cntw[wid][y0], __popc(mm0));
    unsigned mm1 = 0;
    if (v1) {
        mm1 = __match_any_sync(__activemask(), y1);
        if (lane == __ffs(mm1) - 1) atomicAdd(&cntw[6 + wid][y1], __popc(mm1));
    }
    __syncthreads();   // barrier A: counts complete

    float bp0 = 0.1f * (float)__popcll(ymask & ((1ull << y0) - 1ull));
    float bp1 = 0.1f * (float)__popcll(ymask & ((1ull << y1) - 1ull));

    // in-place transform: cntw[s][y] -> count in slots < s; tot[y] = total
    if (tid < 52) {
        int run = 0;
        #pragma unroll
        for (int w2 = 0; w2 < 12; w2++) {
            int c = cntw[w2][tid];
            cntw[w2][tid] = run;
            run += c;
        }
        tot[tid] = run;
    }
    __syncthreads();   // barrier B: prefixes + tot ready

    // warp-parallel exclusive scan of 52 bins (warp 0)
    if (tid < 32) {
        int a0 = tot[tid];
        int v = a0;
        #pragma unroll
        for (int o = 1; o < 32; o <<= 1) {
            int n = __shfl_up_sync(0xffffffffu, v, o);
            if (tid >= o) v += n;
        }
        basev[tid] = v - a0;
        int c32 = __shfl_sync(0xffffffffu, v, 31);
        int a1 = (tid < 20) ? tot[32 + tid] : 0;
        int w = a1;
        #pragma unroll
        for (int o = 1; o < 32; o <<= 1) {
            int n = __shfl_up_sync(0xffffffffu, w, o);
            if (tid >= o) w += n;
        }
        if (tid < 20) basev[32 + tid] = c32 + w - a1;
    }
    __syncthreads();   // barrier C: basev ready

    // ---- scatter: sorted scalars + direct ext4 component writes ----
    {
        int pos = basev[y0] + cntw[wid][y0] + __popc(mm0 & ((1u << lane) - 1u));
        zs[pos] = z0; bs[pos] = bp0;
        gsA[pos] = (short)basev[y0];
        geA[pos] = (short)(basev[y0] + tot[y0]);
        int qp = pos >> 1;
        if (pos & 1) { ext4[qp].y = z0; ext4[qp].w = bp0; }
        else         { ext4[qp].x = z0; ext4[qp].z = bp0; }
        if (pos <= 192) {
            int qd = (pos + NM1) >> 1;
            if (pos & 1) { ext4[qd].x = z0; ext4[qd].z = bp0; }
            else         { ext4[qd].y = z0; ext4[qd].w = bp0; }
        }
    }
    if (v1) {
        int pos = basev[y1] + cntw[6 + wid][y1] + __popc(mm1 & ((1u << lane) - 1u));
        zs[pos] = z1; bs[pos] = bp1;
        gsA[pos] = (short)basev[y1];
        geA[pos] = (short)(basev[y1] + tot[y1]);
        int qp = pos >> 1;
        if (pos & 1) { ext4[qp].y = z1; ext4[qp].w = bp1; }
        else         { ext4[qp].x = z1; ext4[qp].z = bp1; }
        if (pos <= 192) {
            int qd = (pos + NM1) >> 1;
            if (pos & 1) { ext4[qd].x = z1; ext4[qd].z = bp1; }
            else         { ext4[qd].y = z1; ext4[qd].w = bp1; }
        }
    }
    __syncthreads();   // barrier D: sorted arrays + ext4 ready

    // ---- means + variance contributions ----
    float2 s1 = bred2(make_float2(z0 + (v1 ? z1 : 0.f), bp0 + (v1 ? bp1 : 0.f)),
                      (float2*)redbuf, tid);
    float zm = s1.x * (1.0f / (float)NM1);
    float bm = s1.y * (1.0f / (float)NM1);
    float dz0 = z0 - zm, db0 = bp0 - bm;
    float vsum = dz0 * dz0 + db0 * db0;
    if (v1) {
        float dz1 = z1 - zm, db1 = bp1 - bm;
        vsum += dz1 * dz1 + db1 * db1;
    }

    // ---- cross term: j0=2t, j1=2t+1 share 95 extended pairs [t+1 .. t+95] ----
    float accC = 0.f;
    if (tid <= 190) {
        int t = tid;
        float zj0 = zs[2 * t],     bj0 = bs[2 * t];
        float zj1 = zs[2 * t + 1], bj1 = bs[2 * t + 1];
        unsigned long long nz0 = pk2(-zj0, -zj0), nb0 = pk2(-bj0, -bj0);
        unsigned long long nz1 = pk2(-zj1, -zj1), nb1 = pk2(-bj1, -bj1);
        unsigned long long aA = 0ull, aB = 0ull;
        unsigned int addr = (unsigned int)__cvta_generic_to_shared(&ext4[t + 1]);
        #pragma unroll 5
        for (int q = 0; q < 95; q++) {
            unsigned long long zk2, bk2;
            asm("ld.shared.v2.b64 {%0, %1}, [%2];" : "=l"(zk2), "=l"(bk2) : "r"(addr));
            addr += 16;
            aA = fma2p(abs2(add2(zk2, nz0)), abs2(add2(bk2, nb0)), aA);
            aB = fma2p(abs2(add2(zk2, nz1)), abs2(add2(bk2, nb1)), aB);
        }
        accC = lanesum(aA) + lanesum(aB);
        // edge pair (j0, j1)
        accC += fabsf((zj1 - zj0) * (bj1 - bj0));
        // trailing single for j1: element 2t+192 (mod 383)
        {
            int ke = 2 * t + 192; if (ke >= NM1) ke -= NM1;
            accC += fabsf((zs[ke] - zj1) * (bs[ke] - bj1));
        }
        // redistributed pair (382, t)
        accC += fabsf((zs[382] - zs[t]) * (bs[382] - bs[t]));
    }

    // ---- pos correction: same-y groups of p0 and p1 ----
    float accP = 0.f, accQ = 0.f;
    {
        float zj = zs[tid];
        int g0 = gsA[tid], g1 = geA[tid];
        for (int kk = g0; kk < g1; kk++) {
            float d = fabsf(zs[kk] - zj);
            accP += __fdividef(d, 1.0f + __expf(0.1f - d));
            accQ = fmaf(d, d, accQ);
        }
    }
    if (v1) {
        int p1 = tid + 192;
        float zj = zs[p1];
        int g0 = gsA[p1], g1 = geA[p1];
        for (int kk = g0; kk < g1; kk++) {
            float d = fabsf(zs[kk] - zj);
            accP += __fdividef(d, 1.0f + __expf(0.1f - d));
            accQ = fmaf(d, d, accQ);
        }
    }

    float4 s2 = bred4(make_float4(vsum, accC, accP, accQ), redbuf, tid);

    if (tid == 0) {
        float total = (2.0f * (float)NM1) * s2.x - 4.0f * s2.y + s2.z - s2.w;
        g_row[i] = total;
    }

    // ---- fused final reduction ----
    if (tid == 0) {
        __threadfence();
        int old = atomicAdd(&g_cnt, 1);
        isLast = (old == NROW - 1);
    }
    __syncthreads();
    if (isLast) {
        if (tid < 128) {
            dred[tid] = (double)g_row[tid] + (double)g_row[tid + 128]
                      + (double)g_row[tid + 256];
        }
        __syncthreads();
        #pragma unroll
        for (int st = 64; st > 0; st >>= 1) {
            if (tid < st) dred[tid] += dred[tid + st];
            __syncthreads();
        }
        if (tid == 0) {
            out[0] = (float)(dred[0] / MDEN);
            g_cnt = 0;                          // reset for graph replay
        }
    }
}

// ---------------------------------------------------------------------------
extern "C" void kernel_launch(void* const* d_in, const int* in_sizes, int n_in,
                              void* d_out, int out_size) {
    const float* features = (const float*)d_in[0];   // [192, 2, 1024] f32
    const int*   labels   = (const int*)d_in[1];     // [192, 1] i32
    (void)in_sizes; (void)n_in; (void)out_size;      // d_in[2] (ranks) unused

    gram_kernel<<<144, 256>>>(features);
    row_kernel<<<NROW, 192>>>(labels, (float*)d_out);
}